// round 1
// baseline (speedup 1.0000x reference)
#include <cuda_runtime.h>
#include <math_constants.h>

#define Bb 8
#define Ss 1024
#define Dd 1024
#define Hh 16
#define DKk 64
#define DVv 64

// Scratch (allocation-free rule): q/k/v in [B,H,S,64], attn out in [B,S,H*64]
__device__ float g_q[Bb*Hh*Ss*DKk];
__device__ float g_k[Bb*Hh*Ss*DKk];
__device__ float g_v[Bb*Hh*Ss*DVv];
__device__ float g_attn[Bb*Ss*Hh*DVv];

// ---------------------------------------------------------------------------
// GEMM: C = A[M,K] @ W[K,N] + bias.  M=8192, N=1024, K=1024.
// MODE 0: plain row-major [M,N].  MODE 1: scatter to [B,H,S,64] (n=h*64+dk).
// BM=BN=64, BK=32, 256 threads, each thread a 4x4 microtile.
// ---------------------------------------------------------------------------
template<int MODE>
__global__ __launch_bounds__(256)
void gemm_kernel(const float* __restrict__ A, const float* __restrict__ W,
                 const float* __restrict__ bias, float* __restrict__ Cout)
{
    const int N = 1024, K = 1024;
    const int BM = 64, BN = 64, BK = 32;
    __shared__ float As[BK * BM];   // [k][m] (transposed)
    __shared__ float Bs[BK * BN];   // [k][n]

    const int tid = threadIdx.x;
    const int tx = tid & 15;
    const int ty = tid >> 4;
    const int m0 = blockIdx.y * BM;
    const int n0 = blockIdx.x * BN;

    float acc[4][4] = {};

    for (int k0 = 0; k0 < K; k0 += BK) {
        // Load A tile (64 rows x 32 cols) -> transposed smem
        #pragma unroll
        for (int it = 0; it < 2; ++it) {
            int l   = tid * 4 + it * 1024;      // over 2048 elements
            int row = l >> 5;                   // /32
            int col = l & 31;
            float4 a = *(const float4*)(A + (size_t)(m0 + row) * K + k0 + col);
            As[(col + 0) * BM + row] = a.x;
            As[(col + 1) * BM + row] = a.y;
            As[(col + 2) * BM + row] = a.z;
            As[(col + 3) * BM + row] = a.w;
        }
        // Load W tile (32 rows x 64 cols) -> natural smem
        #pragma unroll
        for (int it = 0; it < 2; ++it) {
            int l   = tid * 4 + it * 1024;
            int row = l >> 6;                   // /64
            int col = l & 63;
            *(float4*)(Bs + row * BN + col) =
                *(const float4*)(W + (size_t)(k0 + row) * N + n0 + col);
        }
        __syncthreads();

        #pragma unroll
        for (int kk = 0; kk < BK; ++kk) {
            float4 a4 = *(const float4*)(As + kk * BM + ty * 4);
            float4 b4 = *(const float4*)(Bs + kk * BN + tx * 4);
            float av[4] = {a4.x, a4.y, a4.z, a4.w};
            float bv[4] = {b4.x, b4.y, b4.z, b4.w};
            #pragma unroll
            for (int i = 0; i < 4; ++i)
                #pragma unroll
                for (int j = 0; j < 4; ++j)
                    acc[i][j] += av[i] * bv[j];
        }
        __syncthreads();
    }

    // Epilogue
    float4 bb = *(const float4*)(bias + n0 + tx * 4);
    float bv[4] = {bb.x, bb.y, bb.z, bb.w};

    #pragma unroll
    for (int i = 0; i < 4; ++i) {
        int m = m0 + ty * 4 + i;
        float4 r = make_float4(acc[i][0] + bv[0], acc[i][1] + bv[1],
                               acc[i][2] + bv[2], acc[i][3] + bv[3]);
        if (MODE == 0) {
            *(float4*)(Cout + (size_t)m * N + n0 + tx * 4) = r;
        } else {
            int n  = n0 + tx * 4;
            int h  = n >> 6;
            int dk = n & 63;
            int b  = m >> 10;
            int s  = m & 1023;
            *(float4*)(Cout + ((((size_t)b * Hh + h) * Ss + s) * 64 + dk)) = r;
        }
    }
}

// ---------------------------------------------------------------------------
// Flash attention: one block per (bh, 64-query tile). Online softmax.
// Q/K in smem transposed [d][row]; P overwrites the K buffer for the PV GEMM.
// ---------------------------------------------------------------------------
__global__ __launch_bounds__(256)
void attn_kernel(const float* __restrict__ Q, const float* __restrict__ Kg,
                 const float* __restrict__ Vg, const int* __restrict__ masks,
                 float* __restrict__ Og)
{
    __shared__ float Qs[64 * 64];   // [d][r], pre-scaled by 1/8
    __shared__ float Ks[64 * 64];   // [d][c]; reused as Ps [c][r]
    __shared__ float Vs[64 * 64];   // [c][v]

    const int tid = threadIdx.x;
    const int tx = tid & 15;
    const int ty = tid >> 4;
    const int bh = blockIdx.y;           // 0..127
    const int b  = bh >> 4;
    const int h  = bh & 15;
    const int q0 = blockIdx.x * 64;
    const float scale = 0.125f;          // 1/sqrt(64)

    // Load Q tile (scaled) into transposed smem
    {
        const float* qbase = Q + ((size_t)bh * Ss + q0) * DKk;
        #pragma unroll
        for (int it = 0; it < 4; ++it) {
            int l   = tid * 4 + it * 1024;   // over 4096
            int row = l >> 6;
            int col = l & 63;
            float4 a = *(const float4*)(qbase + row * 64 + col);
            Qs[(col + 0) * 64 + row] = a.x * scale;
            Qs[(col + 1) * 64 + row] = a.y * scale;
            Qs[(col + 2) * 64 + row] = a.z * scale;
            Qs[(col + 3) * 64 + row] = a.w * scale;
        }
    }

    float m_old[4], l_sum[4], o[4][4] = {};
    #pragma unroll
    for (int i = 0; i < 4; ++i) { m_old[i] = -CUDART_INF_F; l_sum[i] = 0.0f; }

    for (int kt = 0; kt < 16; ++kt) {
        __syncthreads();   // previous PV-GEMM done before overwriting Ks/Vs

        // Load K tile (transposed) and V tile (natural)
        const float* kbase = Kg + ((size_t)bh * Ss + kt * 64) * DKk;
        const float* vbase = Vg + ((size_t)bh * Ss + kt * 64) * DVv;
        #pragma unroll
        for (int it = 0; it < 4; ++it) {
            int l   = tid * 4 + it * 1024;
            int row = l >> 6;
            int col = l & 63;
            float4 a = *(const float4*)(kbase + row * 64 + col);
            Ks[(col + 0) * 64 + row] = a.x;
            Ks[(col + 1) * 64 + row] = a.y;
            Ks[(col + 2) * 64 + row] = a.z;
            Ks[(col + 3) * 64 + row] = a.w;
            *(float4*)(Vs + row * 64 + col) = *(const float4*)(vbase + row * 64 + col);
        }
        __syncthreads();

        // S = (Q/8) @ K^T
        float sacc[4][4] = {};
        #pragma unroll
        for (int d = 0; d < 64; ++d) {
            float4 a4 = *(const float4*)(Qs + d * 64 + ty * 4);
            float4 b4 = *(const float4*)(Ks + d * 64 + tx * 4);
            float av[4] = {a4.x, a4.y, a4.z, a4.w};
            float bv[4] = {b4.x, b4.y, b4.z, b4.w};
            #pragma unroll
            for (int i = 0; i < 4; ++i)
                #pragma unroll
                for (int j = 0; j < 4; ++j)
                    sacc[i][j] += av[i] * bv[j];
        }

        // Mask (key-wise)
        {
            const int* mp = masks + b * Ss + kt * 64 + tx * 4;
            int mm[4] = {mp[0], mp[1], mp[2], mp[3]};
            #pragma unroll
            for (int j = 0; j < 4; ++j)
                if (mm[j] == 0) {
                    #pragma unroll
                    for (int i = 0; i < 4; ++i) sacc[i][j] = -1e9f;
                }
        }

        // Online softmax per row (row spread across 16 lanes in a half-warp)
        float p[4][4];
        #pragma unroll
        for (int i = 0; i < 4; ++i) {
            float rmax = fmaxf(fmaxf(sacc[i][0], sacc[i][1]),
                               fmaxf(sacc[i][2], sacc[i][3]));
            #pragma unroll
            for (int off = 8; off >= 1; off >>= 1)
                rmax = fmaxf(rmax, __shfl_xor_sync(0xffffffffu, rmax, off, 16));

            float mnew = fmaxf(m_old[i], rmax);
            float f = __expf(m_old[i] - mnew);
            float rsum = 0.0f;
            #pragma unroll
            for (int j = 0; j < 4; ++j) {
                p[i][j] = __expf(sacc[i][j] - mnew);
                rsum += p[i][j];
            }
            #pragma unroll
            for (int off = 8; off >= 1; off >>= 1)
                rsum += __shfl_xor_sync(0xffffffffu, rsum, off, 16);

            l_sum[i] = l_sum[i] * f + rsum;
            #pragma unroll
            for (int j = 0; j < 4; ++j) o[i][j] *= f;
            m_old[i] = mnew;
        }

        __syncthreads();   // everyone done reading Ks
        // Write P transposed into Ks buffer: Ps[c][r]
        #pragma unroll
        for (int j = 0; j < 4; ++j)
            #pragma unroll
            for (int i = 0; i < 4; ++i)
                Ks[(tx * 4 + j) * 64 + ty * 4 + i] = p[i][j];
        __syncthreads();

        // O += P @ V
        #pragma unroll
        for (int c = 0; c < 64; ++c) {
            float4 a4 = *(const float4*)(Ks + c * 64 + ty * 4);
            float4 b4 = *(const float4*)(Vs + c * 64 + tx * 4);
            float av[4] = {a4.x, a4.y, a4.z, a4.w};
            float bv[4] = {b4.x, b4.y, b4.z, b4.w};
            #pragma unroll
            for (int i = 0; i < 4; ++i)
                #pragma unroll
                for (int j = 0; j < 4; ++j)
                    o[i][j] += av[i] * bv[j];
        }
    }

    // Epilogue: normalize, write [B,S,H*64]
    #pragma unroll
    for (int i = 0; i < 4; ++i) {
        float inv = 1.0f / l_sum[i];
        int srow = q0 + ty * 4 + i;
        float4 r = make_float4(o[i][0] * inv, o[i][1] * inv,
                               o[i][2] * inv, o[i][3] * inv);
        *(float4*)(Og + ((size_t)b * Ss + srow) * 1024 + h * 64 + tx * 4) = r;
    }
}

// ---------------------------------------------------------------------------
extern "C" void kernel_launch(void* const* d_in, const int* in_sizes, int n_in,
                              void* d_out, int out_size)
{
    const float* x     = (const float*)d_in[0];
    const int*   masks = (const int*)  d_in[1];
    const float* Wq    = (const float*)d_in[2];
    const float* bq    = (const float*)d_in[3];
    const float* Wk    = (const float*)d_in[4];
    const float* bk    = (const float*)d_in[5];
    const float* Wv    = (const float*)d_in[6];
    const float* bv    = (const float*)d_in[7];
    const float* Wo    = (const float*)d_in[8];
    const float* bo    = (const float*)d_in[9];
    float* out = (float*)d_out;

    float *q, *k, *v, *attn;
    cudaGetSymbolAddress((void**)&q,    g_q);
    cudaGetSymbolAddress((void**)&k,    g_k);
    cudaGetSymbolAddress((void**)&v,    g_v);
    cudaGetSymbolAddress((void**)&attn, g_attn);

    dim3 gg(1024 / 64, 8192 / 64);   // (N tiles, M tiles)
    gemm_kernel<1><<<gg, 256>>>(x, Wq, bq, q);
    gemm_kernel<1><<<gg, 256>>>(x, Wk, bk, k);
    gemm_kernel<1><<<gg, 256>>>(x, Wv, bv, v);

    attn_kernel<<<dim3(Ss / 64, Bb * Hh), 256>>>(q, k, v, masks, attn);

    gemm_kernel<0><<<gg, 256>>>(attn, Wo, bo, out);
}

// round 3
// speedup vs baseline: 1.4425x; 1.4425x over previous
#include <cuda_runtime.h>
#include <math_constants.h>
#include <cstdint>

#define Bb 8
#define Ss 1024
#define Dd 1024
#define Hh 16
#define DKk 64
#define DVv 64

// Scratch (allocation-free rule): q/k/v in [B,H,S,64], attn out in [B,S,H*64]
__device__ float g_q[Bb*Hh*Ss*DKk];
__device__ float g_k[Bb*Hh*Ss*DKk];
__device__ float g_v[Bb*Hh*Ss*DVv];
__device__ float g_attn[Bb*Ss*Hh*DVv];

__device__ __forceinline__ uint32_t f2tf32(float f) {
    uint32_t r;
    asm("cvt.rna.tf32.f32 %0, %1;" : "=r"(r) : "f"(f));
    return r;
}

#define MMA_TF32(c, A0, A1, A2, A3, B0, B1)                                   \
    asm volatile(                                                             \
        "mma.sync.aligned.m16n8k8.row.col.f32.tf32.tf32.f32 "                 \
        "{%0,%1,%2,%3},{%4,%5,%6,%7},{%8,%9},{%0,%1,%2,%3};"                  \
        : "+f"((c)[0]), "+f"((c)[1]), "+f"((c)[2]), "+f"((c)[3])              \
        : "r"(A0), "r"(A1), "r"(A2), "r"(A3), "r"(B0), "r"(B1))

// ---------------------------------------------------------------------------
// Tensor-core GEMM (tf32, split-A for ~fp32-quality A):
// C = A[M,K] @ W[K,N] + bias.  M=8192, N=1024, K=1024.
// Block tile 128x128, K-step 32. 8 warps: 2(m) x 4(n), warp tile 64x32.
// MODE 0: plain [M,N].  MODE 1: scatter to [B,H,S,64] (n = h*64+dk).
// ---------------------------------------------------------------------------
#define BMg 128
#define BNg 128
#define BKg 32
#define ASTR 36     // 32 + 4 pad -> conflict-free fragment LDS
#define BSTR 136    // 128 + 8 pad -> conflict-free fragment LDS

template<int MODE>
__global__ __launch_bounds__(256)
void gemm_tc(const float* __restrict__ A, const float* __restrict__ W,
             const float* __restrict__ bias, float* __restrict__ Cout)
{
    const int N = 1024, K = 1024;
    __shared__ uint32_t As_hi[BMg * ASTR];
    __shared__ uint32_t As_lo[BMg * ASTR];
    __shared__ uint32_t Bs[BKg * BSTR];

    const int tid  = threadIdx.x;
    const int lane = tid & 31;
    const int wid  = tid >> 5;
    const int wm   = wid & 1;    // 0..1  -> 64-row strip
    const int wn   = wid >> 1;   // 0..3  -> 32-col strip
    const int m0   = blockIdx.y * BMg;
    const int n0   = blockIdx.x * BNg;

    const int lr = lane >> 2;    // 0..7
    const int lc = lane & 3;     // 0..3

    float acc[4][4][4] = {};     // [mt][nt][c0..c3]

    for (int k0 = 0; k0 < K; k0 += BKg) {
        __syncthreads();
        #pragma unroll
        for (int i = 0; i < 4; ++i) {
            int idx = tid + 256 * i;
            // A tile: 128 rows x 32 k
            int ar = idx >> 3, ak = (idx & 7) * 4;
            float4 av = *(const float4*)(A + (size_t)(m0 + ar) * K + k0 + ak);
            uint32_t hx = f2tf32(av.x), hy = f2tf32(av.y),
                     hz = f2tf32(av.z), hw = f2tf32(av.w);
            uint4 hv = make_uint4(hx, hy, hz, hw);
            uint4 lv = make_uint4(
                __float_as_uint(av.x - __uint_as_float(hx)),
                __float_as_uint(av.y - __uint_as_float(hy)),
                __float_as_uint(av.z - __uint_as_float(hz)),
                __float_as_uint(av.w - __uint_as_float(hw)));
            *(uint4*)(As_hi + ar * ASTR + ak) = hv;
            *(uint4*)(As_lo + ar * ASTR + ak) = lv;
            // B tile: 32 k x 128 n
            int bk = idx >> 5, bn = (idx & 31) * 4;
            float4 bv = *(const float4*)(W + (size_t)(k0 + bk) * N + n0 + bn);
            uint4 bb = make_uint4(f2tf32(bv.x), f2tf32(bv.y),
                                  f2tf32(bv.z), f2tf32(bv.w));
            *(uint4*)(Bs + bk * BSTR + bn) = bb;
        }
        __syncthreads();

        #pragma unroll
        for (int kt = 0; kt < 4; ++kt) {
            const int kb = kt * 8;
            uint32_t bf[4][2];
            #pragma unroll
            for (int nt = 0; nt < 4; ++nt) {
                int n  = wn * 32 + nt * 8 + lr;
                int kk = kb + lc;
                bf[nt][0] = Bs[kk * BSTR + n];
                bf[nt][1] = Bs[(kk + 4) * BSTR + n];
            }
            #pragma unroll
            for (int mt = 0; mt < 4; ++mt) {
                int am = wm * 64 + mt * 16 + lr;
                int ak = kb + lc;
                uint32_t ah0 = As_hi[am * ASTR + ak];
                uint32_t ah1 = As_hi[(am + 8) * ASTR + ak];
                uint32_t ah2 = As_hi[am * ASTR + ak + 4];
                uint32_t ah3 = As_hi[(am + 8) * ASTR + ak + 4];
                uint32_t al0 = As_lo[am * ASTR + ak];
                uint32_t al1 = As_lo[(am + 8) * ASTR + ak];
                uint32_t al2 = As_lo[am * ASTR + ak + 4];
                uint32_t al3 = As_lo[(am + 8) * ASTR + ak + 4];
                #pragma unroll
                for (int nt = 0; nt < 4; ++nt) {
                    MMA_TF32(acc[mt][nt], ah0, ah1, ah2, ah3, bf[nt][0], bf[nt][1]);
                    MMA_TF32(acc[mt][nt], al0, al1, al2, al3, bf[nt][0], bf[nt][1]);
                }
            }
        }
    }

    // Epilogue: bias + store (c0,c1) at row, (c2,c3) at row+8
    #pragma unroll
    for (int mt = 0; mt < 4; ++mt) {
        #pragma unroll
        for (int nt = 0; nt < 4; ++nt) {
            int row = m0 + wm * 64 + mt * 16 + lr;
            int col = n0 + wn * 32 + nt * 8 + lc * 2;
            float b0 = bias[col], b1 = bias[col + 1];
            float2 r01 = make_float2(acc[mt][nt][0] + b0, acc[mt][nt][1] + b1);
            float2 r23 = make_float2(acc[mt][nt][2] + b0, acc[mt][nt][3] + b1);
            if (MODE == 0) {
                *(float2*)(Cout + (size_t)row * N + col)       = r01;
                *(float2*)(Cout + (size_t)(row + 8) * N + col) = r23;
            } else {
                int h = col >> 6, dk = col & 63;
                int b  = row >> 10, s  = row & 1023;
                int b2 = (row + 8) >> 10, s2 = (row + 8) & 1023;
                *(float2*)(Cout + ((((size_t)b  * Hh + h) * Ss + s ) * 64 + dk)) = r01;
                *(float2*)(Cout + ((((size_t)b2 * Hh + h) * Ss + s2) * 64 + dk)) = r23;
            }
        }
    }
}

// ---------------------------------------------------------------------------
// Flash attention (unchanged from R1): one block per (bh, 64-query tile).
// ---------------------------------------------------------------------------
__global__ __launch_bounds__(256)
void attn_kernel(const float* __restrict__ Q, const float* __restrict__ Kg,
                 const float* __restrict__ Vg, const int* __restrict__ masks,
                 float* __restrict__ Og)
{
    __shared__ float Qs[64 * 64];   // [d][r], pre-scaled by 1/8
    __shared__ float Ks[64 * 64];   // [d][c]; reused as Ps [c][r]
    __shared__ float Vs[64 * 64];   // [c][v]

    const int tid = threadIdx.x;
    const int tx = tid & 15;
    const int ty = tid >> 4;
    const int bh = blockIdx.y;           // 0..127
    const int b  = bh >> 4;
    const int h  = bh & 15;
    const int q0 = blockIdx.x * 64;
    const float scale = 0.125f;          // 1/sqrt(64)

    {
        const float* qbase = Q + ((size_t)bh * Ss + q0) * DKk;
        #pragma unroll
        for (int it = 0; it < 4; ++it) {
            int l   = tid * 4 + it * 1024;
            int row = l >> 6;
            int col = l & 63;
            float4 a = *(const float4*)(qbase + row * 64 + col);
            Qs[(col + 0) * 64 + row] = a.x * scale;
            Qs[(col + 1) * 64 + row] = a.y * scale;
            Qs[(col + 2) * 64 + row] = a.z * scale;
            Qs[(col + 3) * 64 + row] = a.w * scale;
        }
    }

    float m_old[4], l_sum[4], o[4][4] = {};
    #pragma unroll
    for (int i = 0; i < 4; ++i) { m_old[i] = -CUDART_INF_F; l_sum[i] = 0.0f; }

    for (int kt = 0; kt < 16; ++kt) {
        __syncthreads();

        const float* kbase = Kg + ((size_t)bh * Ss + kt * 64) * DKk;
        const float* vbase = Vg + ((size_t)bh * Ss + kt * 64) * DVv;
        #pragma unroll
        for (int it = 0; it < 4; ++it) {
            int l   = tid * 4 + it * 1024;
            int row = l >> 6;
            int col = l & 63;
            float4 a = *(const float4*)(kbase + row * 64 + col);
            Ks[(col + 0) * 64 + row] = a.x;
            Ks[(col + 1) * 64 + row] = a.y;
            Ks[(col + 2) * 64 + row] = a.z;
            Ks[(col + 3) * 64 + row] = a.w;
            *(float4*)(Vs + row * 64 + col) = *(const float4*)(vbase + row * 64 + col);
        }
        __syncthreads();

        float sacc[4][4] = {};
        #pragma unroll
        for (int d = 0; d < 64; ++d) {
            float4 a4 = *(const float4*)(Qs + d * 64 + ty * 4);
            float4 b4 = *(const float4*)(Ks + d * 64 + tx * 4);
            float av[4] = {a4.x, a4.y, a4.z, a4.w};
            float bv[4] = {b4.x, b4.y, b4.z, b4.w};
            #pragma unroll
            for (int i = 0; i < 4; ++i)
                #pragma unroll
                for (int j = 0; j < 4; ++j)
                    sacc[i][j] += av[i] * bv[j];
        }

        {
            const int* mp = masks + b * Ss + kt * 64 + tx * 4;
            int mm[4] = {mp[0], mp[1], mp[2], mp[3]};
            #pragma unroll
            for (int j = 0; j < 4; ++j)
                if (mm[j] == 0) {
                    #pragma unroll
                    for (int i = 0; i < 4; ++i) sacc[i][j] = -1e9f;
                }
        }

        float p[4][4];
        #pragma unroll
        for (int i = 0; i < 4; ++i) {
            float rmax = fmaxf(fmaxf(sacc[i][0], sacc[i][1]),
                               fmaxf(sacc[i][2], sacc[i][3]));
            #pragma unroll
            for (int off = 8; off >= 1; off >>= 1)
                rmax = fmaxf(rmax, __shfl_xor_sync(0xffffffffu, rmax, off, 16));

            float mnew = fmaxf(m_old[i], rmax);
            float f = __expf(m_old[i] - mnew);
            float rsum = 0.0f;
            #pragma unroll
            for (int j = 0; j < 4; ++j) {
                p[i][j] = __expf(sacc[i][j] - mnew);
                rsum += p[i][j];
            }
            #pragma unroll
            for (int off = 8; off >= 1; off >>= 1)
                rsum += __shfl_xor_sync(0xffffffffu, rsum, off, 16);

            l_sum[i] = l_sum[i] * f + rsum;
            #pragma unroll
            for (int j = 0; j < 4; ++j) o[i][j] *= f;
            m_old[i] = mnew;
        }

        __syncthreads();
        #pragma unroll
        for (int j = 0; j < 4; ++j)
            #pragma unroll
            for (int i = 0; i < 4; ++i)
                Ks[(tx * 4 + j) * 64 + ty * 4 + i] = p[i][j];
        __syncthreads();

        #pragma unroll
        for (int c = 0; c < 64; ++c) {
            float4 a4 = *(const float4*)(Ks + c * 64 + ty * 4);
            float4 b4 = *(const float4*)(Vs + c * 64 + tx * 4);
            float av[4] = {a4.x, a4.y, a4.z, a4.w};
            float bv[4] = {b4.x, b4.y, b4.z, b4.w};
            #pragma unroll
            for (int i = 0; i < 4; ++i)
                #pragma unroll
                for (int j = 0; j < 4; ++j)
                    o[i][j] += av[i] * bv[j];
        }
    }

    #pragma unroll
    for (int i = 0; i < 4; ++i) {
        float inv = 1.0f / l_sum[i];
        int srow = q0 + ty * 4 + i;
        float4 r = make_float4(o[i][0] * inv, o[i][1] * inv,
                               o[i][2] * inv, o[i][3] * inv);
        *(float4*)(Og + ((size_t)b * Ss + srow) * 1024 + h * 64 + tx * 4) = r;
    }
}

// ---------------------------------------------------------------------------
extern "C" void kernel_launch(void* const* d_in, const int* in_sizes, int n_in,
                              void* d_out, int out_size)
{
    const float* x     = (const float*)d_in[0];
    const int*   masks = (const int*)  d_in[1];
    const float* Wq    = (const float*)d_in[2];
    const float* bq    = (const float*)d_in[3];
    const float* Wk    = (const float*)d_in[4];
    const float* bk    = (const float*)d_in[5];
    const float* Wv    = (const float*)d_in[6];
    const float* bv    = (const float*)d_in[7];
    const float* Wo    = (const float*)d_in[8];
    const float* bo    = (const float*)d_in[9];
    float* out = (float*)d_out;

    float *q, *k, *v, *attn;
    cudaGetSymbolAddress((void**)&q,    g_q);
    cudaGetSymbolAddress((void**)&k,    g_k);
    cudaGetSymbolAddress((void**)&v,    g_v);
    cudaGetSymbolAddress((void**)&attn, g_attn);

    dim3 gg(1024 / BNg, 8192 / BMg);   // (8, 64)
    gemm_tc<1><<<gg, 256>>>(x, Wq, bq, q);
    gemm_tc<1><<<gg, 256>>>(x, Wk, bk, k);
    gemm_tc<1><<<gg, 256>>>(x, Wv, bv, v);

    attn_kernel<<<dim3(Ss / 64, Bb * Hh), 256>>>(q, k, v, masks, attn);

    gemm_tc<0><<<gg, 256>>>(attn, Wo, bo, out);
}

// round 4
// speedup vs baseline: 2.2274x; 1.5441x over previous
#include <cuda_runtime.h>
#include <math_constants.h>
#include <cstdint>

#define Bb 8
#define Ss 1024
#define Dd 1024
#define Hh 16
#define DKk 64
#define DVv 64

// Scratch (allocation-free rule): q/k/v in [B,H,S,64], attn out in [B,S,H*64]
__device__ float g_q[Bb*Hh*Ss*DKk];
__device__ float g_k[Bb*Hh*Ss*DKk];
__device__ float g_v[Bb*Hh*Ss*DVv];
__device__ float g_attn[Bb*Ss*Hh*DVv];

__device__ __forceinline__ uint32_t f2tf32(float f) {
    uint32_t r;
    asm("cvt.rna.tf32.f32 %0, %1;" : "=r"(r) : "f"(f));
    return r;
}
__device__ __forceinline__ float tf32f(float f) {
    return __uint_as_float(f2tf32(f));
}

#define MMA_TF32(c, A0, A1, A2, A3, B0, B1)                                   \
    asm volatile(                                                             \
        "mma.sync.aligned.m16n8k8.row.col.f32.tf32.tf32.f32 "                 \
        "{%0,%1,%2,%3},{%4,%5,%6,%7},{%8,%9},{%0,%1,%2,%3};"                  \
        : "+f"((c)[0]), "+f"((c)[1]), "+f"((c)[2]), "+f"((c)[3])              \
        : "r"(A0), "r"(A1), "r"(A2), "r"(A3), "r"(B0), "r"(B1))

// ---------------------------------------------------------------------------
// Tensor-core GEMM (tf32, split-A): C = A[M,K] @ W[K,N] + bias (from R2).
// ---------------------------------------------------------------------------
#define BMg 128
#define BNg 128
#define BKg 32
#define ASTR 36
#define BSTR 136

template<int MODE>
__global__ __launch_bounds__(256)
void gemm_tc(const float* __restrict__ A, const float* __restrict__ W,
             const float* __restrict__ bias, float* __restrict__ Cout)
{
    const int N = 1024, K = 1024;
    __shared__ uint32_t As_hi[BMg * ASTR];
    __shared__ uint32_t As_lo[BMg * ASTR];
    __shared__ uint32_t Bs[BKg * BSTR];

    const int tid  = threadIdx.x;
    const int lane = tid & 31;
    const int wid  = tid >> 5;
    const int wm   = wid & 1;
    const int wn   = wid >> 1;
    const int m0   = blockIdx.y * BMg;
    const int n0   = blockIdx.x * BNg;

    const int lr = lane >> 2;
    const int lc = lane & 3;

    float acc[4][4][4] = {};

    for (int k0 = 0; k0 < K; k0 += BKg) {
        __syncthreads();
        #pragma unroll
        for (int i = 0; i < 4; ++i) {
            int idx = tid + 256 * i;
            int ar = idx >> 3, ak = (idx & 7) * 4;
            float4 av = *(const float4*)(A + (size_t)(m0 + ar) * K + k0 + ak);
            uint32_t hx = f2tf32(av.x), hy = f2tf32(av.y),
                     hz = f2tf32(av.z), hw = f2tf32(av.w);
            uint4 hv = make_uint4(hx, hy, hz, hw);
            uint4 lv = make_uint4(
                __float_as_uint(av.x - __uint_as_float(hx)),
                __float_as_uint(av.y - __uint_as_float(hy)),
                __float_as_uint(av.z - __uint_as_float(hz)),
                __float_as_uint(av.w - __uint_as_float(hw)));
            *(uint4*)(As_hi + ar * ASTR + ak) = hv;
            *(uint4*)(As_lo + ar * ASTR + ak) = lv;
            int bk = idx >> 5, bn = (idx & 31) * 4;
            float4 bv = *(const float4*)(W + (size_t)(k0 + bk) * N + n0 + bn);
            uint4 bb = make_uint4(f2tf32(bv.x), f2tf32(bv.y),
                                  f2tf32(bv.z), f2tf32(bv.w));
            *(uint4*)(Bs + bk * BSTR + bn) = bb;
        }
        __syncthreads();

        #pragma unroll
        for (int kt = 0; kt < 4; ++kt) {
            const int kb = kt * 8;
            uint32_t bf[4][2];
            #pragma unroll
            for (int nt = 0; nt < 4; ++nt) {
                int n  = wn * 32 + nt * 8 + lr;
                int kk = kb + lc;
                bf[nt][0] = Bs[kk * BSTR + n];
                bf[nt][1] = Bs[(kk + 4) * BSTR + n];
            }
            #pragma unroll
            for (int mt = 0; mt < 4; ++mt) {
                int am = wm * 64 + mt * 16 + lr;
                int ak = kb + lc;
                uint32_t ah0 = As_hi[am * ASTR + ak];
                uint32_t ah1 = As_hi[(am + 8) * ASTR + ak];
                uint32_t ah2 = As_hi[am * ASTR + ak + 4];
                uint32_t ah3 = As_hi[(am + 8) * ASTR + ak + 4];
                uint32_t al0 = As_lo[am * ASTR + ak];
                uint32_t al1 = As_lo[(am + 8) * ASTR + ak];
                uint32_t al2 = As_lo[am * ASTR + ak + 4];
                uint32_t al3 = As_lo[(am + 8) * ASTR + ak + 4];
                #pragma unroll
                for (int nt = 0; nt < 4; ++nt) {
                    MMA_TF32(acc[mt][nt], ah0, ah1, ah2, ah3, bf[nt][0], bf[nt][1]);
                    MMA_TF32(acc[mt][nt], al0, al1, al2, al3, bf[nt][0], bf[nt][1]);
                }
            }
        }
    }

    #pragma unroll
    for (int mt = 0; mt < 4; ++mt) {
        #pragma unroll
        for (int nt = 0; nt < 4; ++nt) {
            int row = m0 + wm * 64 + mt * 16 + lr;
            int col = n0 + wn * 32 + nt * 8 + lc * 2;
            float b0 = bias[col], b1 = bias[col + 1];
            float2 r01 = make_float2(acc[mt][nt][0] + b0, acc[mt][nt][1] + b1);
            float2 r23 = make_float2(acc[mt][nt][2] + b0, acc[mt][nt][3] + b1);
            if (MODE == 0) {
                *(float2*)(Cout + (size_t)row * N + col)       = r01;
                *(float2*)(Cout + (size_t)(row + 8) * N + col) = r23;
            } else {
                int h = col >> 6, dk = col & 63;
                int b  = row >> 10, s  = row & 1023;
                int b2 = (row + 8) >> 10, s2 = (row + 8) & 1023;
                *(float2*)(Cout + ((((size_t)b  * Hh + h) * Ss + s ) * 64 + dk)) = r01;
                *(float2*)(Cout + ((((size_t)b2 * Hh + h) * Ss + s2) * 64 + dk)) = r23;
            }
        }
    }
}

// ---------------------------------------------------------------------------
// Tensor-core flash attention. Block = (bh, 64-query tile), 128 threads.
// Each warp: 16 query rows x full 64-col K tile. Online softmax in-warp.
// S: split-Q (2 MMA passes, K rounded once). PV: split-P (2 passes, V rounded).
// Smem strides: 68 for row-major A / K (bank = 4*gid + lc, conflict-free);
//               72 for V (bank = 8*lc + gid, conflict-free).
// ---------------------------------------------------------------------------
#define QSTR 68
#define VSTR 72

__global__ __launch_bounds__(128)
void attn_tc(const float* __restrict__ Q, const float* __restrict__ Kg,
             const float* __restrict__ Vg, const int* __restrict__ masks,
             float* __restrict__ Og)
{
    extern __shared__ float sm[];
    float* Qh = sm;                  // 64 x QSTR
    float* Ql = Qh + 64 * QSTR;      // 64 x QSTR
    float* Ks = Ql + 64 * QSTR;      // 64 x QSTR, reused as Ph
    float* Pl = Ks + 64 * QSTR;      // 64 x QSTR
    float* Vs = Pl + 64 * QSTR;      // 64 x VSTR
    int*   msm = (int*)(Vs + 64 * VSTR);   // 64

    const int tid  = threadIdx.x;
    const int lane = tid & 31;
    const int warp = tid >> 5;       // 0..3
    const int wr   = warp << 4;      // warp row base
    const int gid  = lane >> 2;      // 0..7
    const int lc   = lane & 3;       // 0..3

    const int bh = blockIdx.y;
    const int bb = bh >> 4;
    const int hh = bh & 15;
    const int q0 = blockIdx.x << 6;

    // Load Q tile, scale by 1/8, split into hi/lo
    {
        const float* qb = Q + ((size_t)bh * Ss + q0) * 64;
        #pragma unroll
        for (int i = 0; i < 8; ++i) {
            int idx = tid + (i << 7);
            int r = idx >> 4, c = (idx & 15) << 2;
            float4 a = *(const float4*)(qb + r * 64 + c);
            a.x *= 0.125f; a.y *= 0.125f; a.z *= 0.125f; a.w *= 0.125f;
            float hx = tf32f(a.x), hy = tf32f(a.y), hz = tf32f(a.z), hw = tf32f(a.w);
            float* qh = Qh + r * QSTR + c;
            float* ql = Ql + r * QSTR + c;
            qh[0] = hx;       qh[1] = hy;       qh[2] = hz;       qh[3] = hw;
            ql[0] = a.x - hx; ql[1] = a.y - hy; ql[2] = a.z - hz; ql[3] = a.w - hw;
        }
    }

    float o[8][4] = {};
    float m0 = -CUDART_INF_F, m1 = -CUDART_INF_F;
    float l0 = 0.0f, l1 = 0.0f;

    const int arow0 = (wr + gid) * QSTR;
    const int arow1 = arow0 + 8 * QSTR;

    for (int kt = 0; kt < 16; ++kt) {
        __syncthreads();   // prior tile's PV reads done; Q store visible (kt=0)

        // Load K and V tiles (tf32-rounded once), and mask slice
        const float* kb = Kg + ((size_t)bh * Ss + (kt << 6)) * 64;
        const float* vb = Vg + ((size_t)bh * Ss + (kt << 6)) * 64;
        #pragma unroll
        for (int i = 0; i < 8; ++i) {
            int idx = tid + (i << 7);
            int r = idx >> 4, c = (idx & 15) << 2;
            float4 a = *(const float4*)(kb + r * 64 + c);
            float* kd = Ks + r * QSTR + c;
            kd[0] = tf32f(a.x); kd[1] = tf32f(a.y);
            kd[2] = tf32f(a.z); kd[3] = tf32f(a.w);
            float4 v = *(const float4*)(vb + r * 64 + c);
            float* vd = Vs + r * VSTR + c;
            vd[0] = tf32f(v.x); vd[1] = tf32f(v.y);
            vd[2] = tf32f(v.z); vd[3] = tf32f(v.w);
        }
        if (tid < 64) msm[tid] = masks[bb * Ss + (kt << 6) + tid];
        __syncthreads();

        // S = (Q/8) @ K^T : 2-pass split-Q
        float s[8][4] = {};
        #pragma unroll
        for (int ks = 0; ks < 8; ++ks) {
            const int kc = (ks << 3) + lc;
            uint32_t ah0 = __float_as_uint(Qh[arow0 + kc]);
            uint32_t ah1 = __float_as_uint(Qh[arow1 + kc]);
            uint32_t ah2 = __float_as_uint(Qh[arow0 + kc + 4]);
            uint32_t ah3 = __float_as_uint(Qh[arow1 + kc + 4]);
            uint32_t al0 = __float_as_uint(Ql[arow0 + kc]);
            uint32_t al1 = __float_as_uint(Ql[arow1 + kc]);
            uint32_t al2 = __float_as_uint(Ql[arow0 + kc + 4]);
            uint32_t al3 = __float_as_uint(Ql[arow1 + kc + 4]);
            #pragma unroll
            for (int nt = 0; nt < 8; ++nt) {
                const int nb = ((nt << 3) + gid) * QSTR;
                uint32_t b0 = __float_as_uint(Ks[nb + kc]);
                uint32_t b1 = __float_as_uint(Ks[nb + kc + 4]);
                MMA_TF32(s[nt], ah0, ah1, ah2, ah3, b0, b1);
                MMA_TF32(s[nt], al0, al1, al2, al3, b0, b1);
            }
        }

        // Mask + online softmax (rows: wr+gid and wr+gid+8)
        float mx0 = -CUDART_INF_F, mx1 = -CUDART_INF_F;
        #pragma unroll
        for (int nt = 0; nt < 8; ++nt) {
            int col = (nt << 3) + (lc << 1);
            if (msm[col] == 0)     { s[nt][0] = -1e9f; s[nt][2] = -1e9f; }
            if (msm[col + 1] == 0) { s[nt][1] = -1e9f; s[nt][3] = -1e9f; }
            mx0 = fmaxf(mx0, fmaxf(s[nt][0], s[nt][1]));
            mx1 = fmaxf(mx1, fmaxf(s[nt][2], s[nt][3]));
        }
        mx0 = fmaxf(mx0, __shfl_xor_sync(0xffffffffu, mx0, 1));
        mx0 = fmaxf(mx0, __shfl_xor_sync(0xffffffffu, mx0, 2));
        mx1 = fmaxf(mx1, __shfl_xor_sync(0xffffffffu, mx1, 1));
        mx1 = fmaxf(mx1, __shfl_xor_sync(0xffffffffu, mx1, 2));

        float mn0 = fmaxf(m0, mx0), mn1 = fmaxf(m1, mx1);
        float f0 = __expf(m0 - mn0), f1 = __expf(m1 - mn1);
        m0 = mn0; m1 = mn1;

        float sum0 = 0.0f, sum1 = 0.0f;
        #pragma unroll
        for (int nt = 0; nt < 8; ++nt) {
            s[nt][0] = __expf(s[nt][0] - mn0);
            s[nt][1] = __expf(s[nt][1] - mn0);
            s[nt][2] = __expf(s[nt][2] - mn1);
            s[nt][3] = __expf(s[nt][3] - mn1);
            sum0 += s[nt][0] + s[nt][1];
            sum1 += s[nt][2] + s[nt][3];
        }
        sum0 += __shfl_xor_sync(0xffffffffu, sum0, 1);
        sum0 += __shfl_xor_sync(0xffffffffu, sum0, 2);
        sum1 += __shfl_xor_sync(0xffffffffu, sum1, 1);
        sum1 += __shfl_xor_sync(0xffffffffu, sum1, 2);

        l0 = l0 * f0 + sum0;
        l1 = l1 * f1 + sum1;
        #pragma unroll
        for (int nt = 0; nt < 8; ++nt) {
            o[nt][0] *= f0; o[nt][1] *= f0;
            o[nt][2] *= f1; o[nt][3] *= f1;
        }

        __syncthreads();   // all warps finished reading Ks -> reuse as Ph
        float* Ph = Ks;
        #pragma unroll
        for (int nt = 0; nt < 8; ++nt) {
            int col = (nt << 3) + (lc << 1);
            #pragma unroll
            for (int j = 0; j < 2; ++j) {
                float p0 = s[nt][j],     h0 = tf32f(p0);
                float p1 = s[nt][2 + j], h1 = tf32f(p1);
                Ph[arow0 + col + j] = h0; Pl[arow0 + col + j] = p0 - h0;
                Ph[arow1 + col + j] = h1; Pl[arow1 + col + j] = p1 - h1;
            }
        }
        __syncwarp();      // PV A-fragments only read this warp's own 16 rows

        // O += P @ V : 2-pass split-P
        #pragma unroll
        for (int ks = 0; ks < 8; ++ks) {
            const int kc = (ks << 3) + lc;
            uint32_t ah0 = __float_as_uint(Ph[arow0 + kc]);
            uint32_t ah1 = __float_as_uint(Ph[arow1 + kc]);
            uint32_t ah2 = __float_as_uint(Ph[arow0 + kc + 4]);
            uint32_t ah3 = __float_as_uint(Ph[arow1 + kc + 4]);
            uint32_t al0 = __float_as_uint(Pl[arow0 + kc]);
            uint32_t al1 = __float_as_uint(Pl[arow1 + kc]);
            uint32_t al2 = __float_as_uint(Pl[arow0 + kc + 4]);
            uint32_t al3 = __float_as_uint(Pl[arow1 + kc + 4]);
            #pragma unroll
            for (int nt = 0; nt < 8; ++nt) {
                const int nb = (nt << 3) + gid;
                uint32_t b0 = __float_as_uint(Vs[kc * VSTR + nb]);
                uint32_t b1 = __float_as_uint(Vs[(kc + 4) * VSTR + nb]);
                MMA_TF32(o[nt], ah0, ah1, ah2, ah3, b0, b1);
                MMA_TF32(o[nt], al0, al1, al2, al3, b0, b1);
            }
        }
    }

    // Epilogue: normalize, write [B,S,H*64]
    float inv0 = 1.0f / l0, inv1 = 1.0f / l1;
    size_t r0 = (size_t)q0 + wr + gid;
    float* ob = Og + ((size_t)bb * Ss) * 1024 + hh * 64;
    #pragma unroll
    for (int nt = 0; nt < 8; ++nt) {
        int col = (nt << 3) + (lc << 1);
        *(float2*)(ob + r0 * 1024 + col) =
            make_float2(o[nt][0] * inv0, o[nt][1] * inv0);
        *(float2*)(ob + (r0 + 8) * 1024 + col) =
            make_float2(o[nt][2] * inv1, o[nt][3] * inv1);
    }
}

#define ATTN_SMEM ((4 * 64 * QSTR + 64 * VSTR) * 4 + 64 * 4)

// ---------------------------------------------------------------------------
extern "C" void kernel_launch(void* const* d_in, const int* in_sizes, int n_in,
                              void* d_out, int out_size)
{
    const float* x     = (const float*)d_in[0];
    const int*   masks = (const int*)  d_in[1];
    const float* Wq    = (const float*)d_in[2];
    const float* bq    = (const float*)d_in[3];
    const float* Wk    = (const float*)d_in[4];
    const float* bk    = (const float*)d_in[5];
    const float* Wv    = (const float*)d_in[6];
    const float* bv    = (const float*)d_in[7];
    const float* Wo    = (const float*)d_in[8];
    const float* bo    = (const float*)d_in[9];
    float* out = (float*)d_out;

    float *q, *k, *v, *attn;
    cudaGetSymbolAddress((void**)&q,    g_q);
    cudaGetSymbolAddress((void**)&k,    g_k);
    cudaGetSymbolAddress((void**)&v,    g_v);
    cudaGetSymbolAddress((void**)&attn, g_attn);

    static bool attr_set = false;
    if (!attr_set) {
        cudaFuncSetAttribute(attn_tc,
            cudaFuncAttributeMaxDynamicSharedMemorySize, ATTN_SMEM);
        attr_set = true;
    }

    dim3 gg(1024 / BNg, 8192 / BMg);   // (8, 64)
    gemm_tc<1><<<gg, 256>>>(x, Wq, bq, q);
    gemm_tc<1><<<gg, 256>>>(x, Wk, bk, k);
    gemm_tc<1><<<gg, 256>>>(x, Wv, bv, v);

    attn_tc<<<dim3(Ss / 64, Bb * Hh), 128, ATTN_SMEM>>>(q, k, v, masks, attn);

    gemm_tc<0><<<gg, 256>>>(attn, Wo, bo, out);
}